// round 15
// baseline (speedup 1.0000x reference)
#include <cuda_runtime.h>
#include <cuda_fp16.h>
#include <cstdint>
#include <math.h>

#define BB 2
#define SS 2048
#define DD 768
#define HH 12
#define DKK 64
#define DFF 3072
#define MROWS (BB*SS)   // 4096

// ======================= device scratch (no allocs allowed) ================
__device__ float g_p[4*MROWS*DD];   // split-K partials (bias folded into z=0)
__device__ float g_x[MROWS*DD];     // post-LN1 fp32 (residual for LN2)
// fp16 activations / weights
__device__ __half s_srch[MROWS*DD];
__device__ __half s_ctxh[MROWS*DD];
__device__ __half s_xh[MROWS*DD];
__device__ __half s_ffh[MROWS*DFF];
__device__ __half a_q[BB*HH*SS*DKK];
__device__ __half a_k[BB*HH*SS*DKK];
__device__ __half a_v[BB*HH*SS*DKK];
__device__ __half w_qkv[3*DD*DD];   // [2304, 768]
__device__ __half w_o[DD*DD];
__device__ __half w_1[DFF*DD];
__device__ __half w_2[DD*DFF];

// ======================= PTX helpers (stable ISA only) =====================
__device__ __forceinline__ uint32_t smem_u32(const void* p) {
    uint32_t a;
    asm("{ .reg .u64 t; cvta.to.shared.u64 t, %1; cvt.u32.u64 %0, t; }" : "=r"(a) : "l"(p));
    return a;
}
#define CP_ASYNC16(dst, src) \
    asm volatile("cp.async.cg.shared.global [%0], [%1], 16;" :: "r"(dst), "l"(src) : "memory")
#define CP_COMMIT() asm volatile("cp.async.commit_group;" ::: "memory")
#define CP_WAIT(n)  asm volatile("cp.async.wait_group %0;" :: "n"(n) : "memory")

__device__ __forceinline__ void ldm_x4(uint32_t* r, uint32_t addr) {
    asm volatile("ldmatrix.sync.aligned.m8n8.x4.shared.b16 {%0,%1,%2,%3}, [%4];"
        : "=r"(r[0]), "=r"(r[1]), "=r"(r[2]), "=r"(r[3]) : "r"(addr));
}
__device__ __forceinline__ void ldm_x4_t(uint32_t* r, uint32_t addr) {
    asm volatile("ldmatrix.sync.aligned.m8n8.x4.trans.shared.b16 {%0,%1,%2,%3}, [%4];"
        : "=r"(r[0]), "=r"(r[1]), "=r"(r[2]), "=r"(r[3]) : "r"(addr));
}
__device__ __forceinline__ void mma_f16(float* c, const uint32_t* a, const uint32_t* b) {
    asm volatile("mma.sync.aligned.m16n8k16.row.col.f32.f16.f16.f32 "
        "{%0,%1,%2,%3}, {%4,%5,%6,%7}, {%8,%9}, {%0,%1,%2,%3};"
        : "+f"(c[0]), "+f"(c[1]), "+f"(c[2]), "+f"(c[3])
        : "r"(a[0]), "r"(a[1]), "r"(a[2]), "r"(a[3]), "r"(b[0]), "r"(b[1]));
}
__device__ __forceinline__ float ex2(float x) {
    float y; asm("ex2.approx.ftz.f32 %0, %1;" : "=f"(y) : "f"(x)); return y;
}
__device__ __forceinline__ uint32_t pack_h2(float v0, float v1) {
    uint32_t r;
    asm("cvt.rn.f16x2.f32 %0, %1, %2;" : "=r"(r) : "f"(v1), "f"(v0));
    return r;
}

static __device__ __constant__ const float QSCALE_D = 0.125f * 1.44269504088896340736f;

// ======================= fused preprocessing kernel ========================
static constexpr int NCVT = (MROWS * DD) / 256;   // 12288
static constexpr int NQKV = 2 * 24 * 3 * HH;      // 1728
static constexpr int NWO  = 24 * 24;              // 576
static constexpr int NW1  = 96 * 24;              // 2304
static constexpr int NW2  = 24 * 96;              // 2304
static constexpr int PRE_GRID = NCVT + NQKV + NWO + NW1 + NW2;

__global__ void preproc(const float* __restrict__ src,
                        const float* __restrict__ Wq, const float* __restrict__ Wk,
                        const float* __restrict__ Wv, const float* __restrict__ Wo,
                        const float* __restrict__ W1, const float* __restrict__ W2)
{
    int blk = blockIdx.x;
    if (blk < NCVT) {
        int i = blk * 256 + threadIdx.x;
        s_srch[i] = __float2half_rn(src[i]);
        return;
    }
    blk -= NCVT;

    __shared__ float t[32][33];
    const int tx = threadIdx.x & 31, ty = threadIdx.x >> 5;

    const float* W; __half* o;
    int n0, k0, Kst;
    size_t rowoff = 0;
    if (blk < NQKV) {
        const int z = blk / 48, rem = blk % 48;
        const int sel = z / HH, h = z % HH;
        W = (sel == 0 ? Wq : sel == 1 ? Wk : Wv) + (size_t)h * DD * DKK;
        n0 = (rem % 2) * 32;
        k0 = (rem / 2) * 32;
        Kst = DD;
        o = w_qkv;
        rowoff = (size_t)sel * DD + h * DKK;
        #pragma unroll
        for (int r = 0; r < 4; r++)
            t[ty + 8 * r][tx] = W[(size_t)(k0 + ty + 8 * r) * DKK + n0 + tx];
        __syncthreads();
        #pragma unroll
        for (int r = 0; r < 4; r++)
            o[(rowoff + n0 + ty + 8 * r) * Kst + k0 + tx] =
                __float2half_rn(t[tx][ty + 8 * r]);
        return;
    }
    blk -= NQKV;
    int N;
    if (blk < NWO)      { W = Wo; o = w_o; N = DD;  Kst = DD;  n0 = (blk % 24) * 32; k0 = (blk / 24) * 32; }
    else if ((blk -= NWO) < NW1) { W = W1; o = w_1; N = DFF; Kst = DD;  n0 = (blk % 96) * 32; k0 = (blk / 96) * 32; }
    else                { blk -= NW1; W = W2; o = w_2; N = DD; Kst = DFF; n0 = (blk % 24) * 32; k0 = (blk / 24) * 32; }
    #pragma unroll
    for (int r = 0; r < 4; r++)
        t[ty + 8 * r][tx] = W[(size_t)(k0 + ty + 8 * r) * N + n0 + tx];
    __syncthreads();
    #pragma unroll
    for (int r = 0; r < 4; r++)
        o[(size_t)(n0 + ty + 8 * r) * Kst + k0 + tx] = __float2half_rn(t[tx][ty + 8 * r]);
}

// ======================= mma.sync fp16 GEMM (3-stage pipeline) =============
// MODE 2: relu(acc+bias) -> fp16 row-major
// MODE 4: fused QKV epilogue: Q (scaled) / K / V fp16 [B,H,S,DK]
// MODE 5: split-K partial: acc (+bias iff z==0) -> fp32 at C + z*M*N
static constexpr int RS = 80;
static constexpr int NSTG = 3;

template<int BN> struct GP {
    static constexpr int A_BYTES = 128 * RS;
    static constexpr int B_BYTES = BN * RS;
    static constexpr int STGB    = A_BYTES + B_BYTES;
    static constexpr int SMEM    = NSTG * STGB;
    static constexpr int NTW     = BN / 16;
    static constexpr int NPB     = BN / 32;
    static constexpr int CPT     = (512 + 4 * BN) / 256;
};

template<int MODE, int BN, int MINB>
__global__ void __launch_bounds__(256, MINB) gemm_mma(
    const __half* __restrict__ A, const __half* __restrict__ B,
    const float* __restrict__ bias, const float* __restrict__ res,
    float* __restrict__ C, __half* __restrict__ Cs,
    int M, int N, int K)
{
    using P = GP<BN>;
    extern __shared__ char sb[];
    const uint32_t sbu = smem_u32(sb);
    const int tid  = threadIdx.x;
    const int wid  = tid >> 5;
    const int lane = tid & 31;
    const int wm   = wid & 3;
    const int wn   = wid >> 2;

    const int z      = (MODE == 5) ? blockIdx.z : 0;
    const int kLen   = (MODE == 5) ? K / ((int)gridDim.z) : K;
    const int kc0    = z * kLen;

    const int rowBase = blockIdx.y << 7;
    const int colBase = blockIdx.x * BN;
    const __half* gA = A + (size_t)rowBase * K;
    const __half* gB = B + (size_t)colBase * K;

    int ld_mat[P::CPT], ld_r[P::CPT], ld_q[P::CPT];
    #pragma unroll
    for (int i = 0; i < P::CPT; i++) {
        int slot = (i << 8) + tid;
        int mat, rem;
        if (slot < 512) { mat = 0; rem = slot; }
        else            { mat = 1; rem = slot - 512; }
        ld_mat[i] = mat; ld_r[i] = rem >> 2; ld_q[i] = rem & 3;
    }

    auto load_stage = [&](int kc, int buf) {
        const uint32_t base = sbu + buf * P::STGB;
        #pragma unroll
        for (int i = 0; i < P::CPT; i++) {
            const __half* src = (ld_mat[i] == 0 ? gA : gB)
                                + (size_t)ld_r[i] * K + kc + (ld_q[i] << 3);
            uint32_t dst = base + ld_mat[i] * P::A_BYTES + ld_r[i] * RS + (ld_q[i] << 4);
            CP_ASYNC16(dst, src);
        }
        CP_COMMIT();
    };

    float acc[2][P::NTW][4];
    #pragma unroll
    for (int mt = 0; mt < 2; mt++)
        #pragma unroll
        for (int nt = 0; nt < P::NTW; nt++)
            #pragma unroll
            for (int j = 0; j < 4; j++) acc[mt][nt][j] = 0.0f;

    const uint32_t aAddr = (uint32_t)((wm * 32 + (lane & 15)) * RS + (lane >> 4) * 16);
    const uint32_t bAddr = (uint32_t)((wn * (BN/2) + ((lane >> 4) << 3) + (lane & 7)) * RS
                                      + ((lane >> 3) & 1) * 16);

    const int nStages = kLen >> 5;
    load_stage(kc0, 0);
    if (nStages > 1) load_stage(kc0 + 32, 1);

    int bufC = 0, bufL = 2;
    for (int c = 0; c < nStages; c++) {
        if (c + 1 < nStages) { CP_WAIT(1); } else { CP_WAIT(0); }
        __syncthreads();
        // top barrier proves all warps finished stage c-1 -> its buffer is free
        if (c + 2 < nStages) load_stage(kc0 + ((c + 2) << 5), bufL);

        const uint32_t base = sbu + bufC * P::STGB;
        #pragma unroll
        for (int ks = 0; ks < 2; ks++) {
            const uint32_t ko = ks * 32;
            uint32_t bf[P::NTW*2];
            #pragma unroll
            for (int np = 0; np < P::NPB; np++)
                ldm_x4(bf + np * 4, base + P::A_BYTES + bAddr + np * 16 * RS + ko);
            #pragma unroll
            for (int mt = 0; mt < 2; mt++) {
                uint32_t ah[4];
                ldm_x4(ah, base + aAddr + mt * 16 * RS + ko);
                #pragma unroll
                for (int nt = 0; nt < P::NTW; nt++)
                    mma_f16(acc[mt][nt], ah, bf + nt * 2);
            }
        }
        bufC = (bufC == NSTG - 1) ? 0 : bufC + 1;
        bufL = (bufL == NSTG - 1) ? 0 : bufL + 1;
    }

    // ---------------- epilogue ----------------
    const int g  = lane >> 2;
    const int tc = (lane & 3) << 1;

    #pragma unroll
    for (int mt = 0; mt < 2; mt++) {
        #pragma unroll
        for (int half_i = 0; half_i < 2; half_i++) {
            const int orow = rowBase + wm * 32 + mt * 16 + g + half_i * 8;
            #pragma unroll
            for (int nt = 0; nt < P::NTW; nt++) {
                const int col = colBase + wn * (BN/2) + nt * 8 + tc;
                float a0 = acc[mt][nt][half_i * 2 + 0];
                float a1 = acc[mt][nt][half_i * 2 + 1];
                if (MODE == 4) {
                    const int sel = col / DD;
                    const int lc  = col - sel * DD;
                    const float* bptr = sel == 0 ? bias : sel == 1 ? res : (const float*)C;
                    float v0 = a0 + bptr[lc];
                    float v1 = a1 + bptr[lc + 1];
                    const int b = orow >> 11, s = orow & 2047;
                    const int h = lc >> 6, dk = lc & 63;
                    size_t off = (((size_t)b * HH + h) * SS + s) * DKK + dk;
                    if (sel == 0) { v0 *= QSCALE_D; v1 *= QSCALE_D; }
                    __half* dst = sel == 0 ? a_q : sel == 1 ? a_k : a_v;
                    *(uint32_t*)(dst + off) = pack_h2(v0, v1);
                } else if (MODE == 5) {
                    float b0 = (z == 0) ? bias[col] : 0.0f;
                    float b1 = (z == 0) ? bias[col + 1] : 0.0f;
                    *(float2*)(C + (size_t)z * M * N + (size_t)orow * N + col)
                        = make_float2(a0 + b0, a1 + b1);
                } else {
                    float v0 = fmaxf(a0 + bias[col], 0.0f);
                    float v1 = fmaxf(a1 + bias[col + 1], 0.0f);
                    *(uint32_t*)(Cs + (size_t)orow * N + col) = pack_h2(v0, v1);
                }
            }
        }
    }
}

// ======================= mma.sync flash attention (3-stage KV) =============
static constexpr int ATT_RS  = 144;
static constexpr int ATT_BUF = 64 * ATT_RS;
static constexpr int ATT_STG = 2 * ATT_BUF;        // 18432 (K,V)
static constexpr int ATT_SMEM = NSTG * ATT_STG;    // 55296

__global__ void __launch_bounds__(256, 2) attn_mma(
    const __half* __restrict__ Q, const __half* __restrict__ K,
    const __half* __restrict__ V, __half* __restrict__ Cs)
{
    extern __shared__ char sm[];
    const uint32_t sbu = smem_u32(sm);
    const int qt = blockIdx.x, h = blockIdx.y, b = blockIdx.z;
    const int tid = threadIdx.x, wid = tid >> 5, lane = tid & 31;

    const size_t bh = (size_t)b * HH + h;
    const __half* gQ = Q + (bh * SS + qt * 128) * DKK;
    const __half* gK = K + bh * SS * DKK;
    const __half* gV = V + bh * SS * DKK;

    // ---- stage Q tile (uses buffer-0 region), extract A-frags ----
    {
        #pragma unroll
        for (int i = 0; i < 4; i++) {
            int slot = (i << 8) + tid;
            int r = slot >> 3, c = slot & 7;
            CP_ASYNC16(sbu + r * ATT_RS + (c << 4), gQ + r * DKK + (c << 3));
        }
        CP_COMMIT(); CP_WAIT(0);
        __syncthreads();
    }
    uint32_t qf[4][4];
    {
        const uint32_t qa = sbu + (wid * 16 + (lane & 15)) * ATT_RS + ((lane >> 4) << 4);
        #pragma unroll
        for (int ks = 0; ks < 4; ks++) ldm_x4(qf[ks], qa + ks * 32);
    }
    __syncthreads();

    auto load_kv = [&](int t0, int buf) {
        const uint32_t base = sbu + buf * ATT_STG;
        #pragma unroll
        for (int i = 0; i < 4; i++) {
            int slot = (i << 8) + tid;
            int arr = slot >> 9;
            int rem = slot & 511;
            int r = rem >> 3, c = rem & 7;
            const __half* src = (arr == 0 ? gK : gV) + (size_t)(t0 + r) * DKK + (c << 3);
            CP_ASYNC16(base + arr * ATT_BUF + r * ATT_RS + (c << 4), src);
        }
        CP_COMMIT();
    };

    float ctx[8][4];
    #pragma unroll
    for (int nt = 0; nt < 8; nt++)
        #pragma unroll
        for (int j = 0; j < 4; j++) ctx[nt][j] = 0.0f;
    float m0 = -1e30f, m1 = -1e30f, l0 = 0.0f, l1 = 0.0f;

    const uint32_t kAddr = (uint32_t)(((((lane >> 4) << 3) | (lane & 7)) * ATT_RS)
                                      + ((lane >> 3) & 1) * 16);
    const uint32_t vAddr = (uint32_t)((lane & 15) * ATT_RS + ((lane >> 4) << 4));

    const int nT = SS / 64;
    load_kv(0, 0);
    load_kv(64, 1);
    int bufC = 0, bufL = 2;

    #pragma unroll 1
    for (int t = 0; t < nT; t++) {
        if (t + 1 < nT) { CP_WAIT(1); } else { CP_WAIT(0); }
        __syncthreads();
        if (t + 2 < nT) load_kv((t + 2) * 64, bufL);
        const uint32_t base = sbu + bufC * ATT_STG;

        float sa[8][4];
        #pragma unroll
        for (int nt = 0; nt < 8; nt++)
            #pragma unroll
            for (int j = 0; j < 4; j++) sa[nt][j] = 0.0f;
        #pragma unroll
        for (int ks = 0; ks < 4; ks++) {
            #pragma unroll
            for (int np = 0; np < 4; np++) {
                uint32_t kb[4];
                ldm_x4(kb, base + kAddr + np * 16 * ATT_RS + ks * 32);
                mma_f16(sa[2 * np],     qf[ks], kb);
                mma_f16(sa[2 * np + 1], qf[ks], kb + 2);
            }
        }

        float rm0 = -1e30f, rm1 = -1e30f;
        #pragma unroll
        for (int nt = 0; nt < 8; nt++) {
            rm0 = fmaxf(rm0, fmaxf(sa[nt][0], sa[nt][1]));
            rm1 = fmaxf(rm1, fmaxf(sa[nt][2], sa[nt][3]));
        }
        rm0 = fmaxf(rm0, __shfl_xor_sync(0xFFFFFFFFu, rm0, 1));
        rm0 = fmaxf(rm0, __shfl_xor_sync(0xFFFFFFFFu, rm0, 2));
        rm1 = fmaxf(rm1, __shfl_xor_sync(0xFFFFFFFFu, rm1, 1));
        rm1 = fmaxf(rm1, __shfl_xor_sync(0xFFFFFFFFu, rm1, 2));
        const float nm0 = fmaxf(m0, rm0), nm1 = fmaxf(m1, rm1);
        const float c0 = ex2(m0 - nm0), c1 = ex2(m1 - nm1);
        l0 *= c0; l1 *= c1;
        #pragma unroll
        for (int nt = 0; nt < 8; nt++) {
            ctx[nt][0] *= c0; ctx[nt][1] *= c0;
            ctx[nt][2] *= c1; ctx[nt][3] *= c1;
        }
        float s0 = 0.0f, s1 = 0.0f;
        #pragma unroll
        for (int nt = 0; nt < 8; nt++) {
            float p0 = ex2(sa[nt][0] - nm0); sa[nt][0] = p0; s0 += p0;
            float p1 = ex2(sa[nt][1] - nm0); sa[nt][1] = p1; s0 += p1;
            float p2 = ex2(sa[nt][2] - nm1); sa[nt][2] = p2; s1 += p2;
            float p3 = ex2(sa[nt][3] - nm1); sa[nt][3] = p3; s1 += p3;
        }
        s0 += __shfl_xor_sync(0xFFFFFFFFu, s0, 1);
        s0 += __shfl_xor_sync(0xFFFFFFFFu, s0, 2);
        s1 += __shfl_xor_sync(0xFFFFFFFFu, s1, 1);
        s1 += __shfl_xor_sync(0xFFFFFFFFu, s1, 2);
        l0 += s0; l1 += s1; m0 = nm0; m1 = nm1;

        #pragma unroll
        for (int ks = 0; ks < 4; ks++) {
            uint32_t ph[4];
            ph[0] = pack_h2(sa[2 * ks][0],     sa[2 * ks][1]);
            ph[1] = pack_h2(sa[2 * ks][2],     sa[2 * ks][3]);
            ph[2] = pack_h2(sa[2 * ks + 1][0], sa[2 * ks + 1][1]);
            ph[3] = pack_h2(sa[2 * ks + 1][2], sa[2 * ks + 1][3]);
            const uint32_t vrow = vAddr + ks * 16 * ATT_RS;
            #pragma unroll
            for (int np = 0; np < 4; np++) {
                uint32_t vb[4];
                ldm_x4_t(vb, base + ATT_BUF + vrow + np * 32);
                mma_f16(ctx[2 * np],     ph, vb);
                mma_f16(ctx[2 * np + 1], ph, vb + 2);
            }
        }
        bufC = (bufC == NSTG - 1) ? 0 : bufC + 1;
        bufL = (bufL == NSTG - 1) ? 0 : bufL + 1;
    }

    const float i0 = 1.0f / l0, i1 = 1.0f / l1;
    const int g = lane >> 2, tc2 = (lane & 3) << 1;
    const int r0 = qt * 128 + wid * 16 + g;
    const size_t base0 = ((size_t)b * SS + r0) * DD + h * DKK;
    #pragma unroll
    for (int nt = 0; nt < 8; nt++) {
        const int col = nt * 8 + tc2;
        *(uint32_t*)(Cs + base0 + col) = pack_h2(ctx[nt][0] * i0, ctx[nt][1] * i0);
        *(uint32_t*)(Cs + base0 + (size_t)8 * DD + col) = pack_h2(ctx[nt][2] * i1, ctx[nt][3] * i1);
    }
}

// ======================= LayerNorm over (sum of NP partials + res) =========
template<int NP, int WB>
__global__ __launch_bounds__(256)
void ln_k(const float* __restrict__ parts, const float* __restrict__ res,
          const float* __restrict__ w, const float* __restrict__ bsh,
          float* __restrict__ out, __half* __restrict__ oh)
{
    const size_t row = blockIdx.x;
    float xv[3];
    float s = 0.0f, s2 = 0.0f;
    #pragma unroll
    for (int it = 0; it < 3; it++) {
        int i = threadIdx.x + it * 256;
        float v = res[row * DD + i];
        #pragma unroll
        for (int p = 0; p < NP; p++)
            v += parts[(size_t)p * MROWS * DD + row * DD + i];
        xv[it] = v; s += v; s2 += v * v;
    }
    #pragma unroll
    for (int o = 16; o > 0; o >>= 1) {
        s  += __shfl_xor_sync(0xFFFFFFFFu, s,  o);
        s2 += __shfl_xor_sync(0xFFFFFFFFu, s2, o);
    }
    __shared__ float ws[8], ws2[8];
    const int wid = threadIdx.x >> 5, lane = threadIdx.x & 31;
    if (lane == 0) { ws[wid] = s; ws2[wid] = s2; }
    __syncthreads();
    float ts = 0.0f, ts2 = 0.0f;
    #pragma unroll
    for (int i = 0; i < 8; i++) { ts += ws[i]; ts2 += ws2[i]; }
    const float mu   = ts  * (1.0f / DD);
    const float var  = ts2 * (1.0f / DD) - mu * mu;
    const float rstd = rsqrtf(var + 1e-5f);
    #pragma unroll
    for (int it = 0; it < 3; it++) {
        int i = threadIdx.x + it * 256;
        float r = (xv[it] - mu) * rstd * w[i] + bsh[i];
        if (out) out[row * DD + i] = r;
        if (WB) oh[row * DD + i] = __float2half_rn(r);
    }
}

// ======================= launch ============================================
template<typename T>
static void* sym_addr(T& sym) {
    void* p = nullptr;
    cudaGetSymbolAddress(&p, sym);
    return p;
}

extern "C" void kernel_launch(void* const* d_in, const int* in_sizes, int n_in,
                              void* d_out, int out_size)
{
    const float* src  = (const float*)d_in[0];
    const float* Wq   = (const float*)d_in[1];
    const float* bq   = (const float*)d_in[2];
    const float* Wk   = (const float*)d_in[3];
    const float* bk   = (const float*)d_in[4];
    const float* Wv   = (const float*)d_in[5];
    const float* bv   = (const float*)d_in[6];
    const float* Wo   = (const float*)d_in[7];
    const float* bo   = (const float*)d_in[8];
    const float* ln1w = (const float*)d_in[9];
    const float* ln1b = (const float*)d_in[10];
    const float* W1   = (const float*)d_in[11];
    const float* b1   = (const float*)d_in[12];
    const float* W2   = (const float*)d_in[13];
    const float* b2   = (const float*)d_in[14];
    const float* ln2w = (const float*)d_in[15];
    const float* ln2b = (const float*)d_in[16];
    float* out = (float*)d_out;

    float* pp   = (float*)sym_addr(g_p);
    float* px   = (float*)sym_addr(g_x);

    __half* ctxh = (__half*)sym_addr(s_ctxh);
    __half* srch = (__half*)sym_addr(s_srch);
    __half* xh   = (__half*)sym_addr(s_xh);
    __half* ffh  = (__half*)sym_addr(s_ffh);
    __half* q1   = (__half*)sym_addr(a_q);
    __half* k1   = (__half*)sym_addr(a_k);
    __half* v1   = (__half*)sym_addr(a_v);
    __half* wqkv = (__half*)sym_addr(w_qkv);
    __half* wo   = (__half*)sym_addr(w_o);
    __half* w1   = (__half*)sym_addr(w_1);
    __half* w2   = (__half*)sym_addr(w_2);

    cudaFuncSetAttribute((const void*)gemm_mma<4,128,2>, cudaFuncAttributeMaxDynamicSharedMemorySize, GP<128>::SMEM);
    cudaFuncSetAttribute((const void*)gemm_mma<2,128,2>, cudaFuncAttributeMaxDynamicSharedMemorySize, GP<128>::SMEM);
    cudaFuncSetAttribute((const void*)gemm_mma<5,128,2>, cudaFuncAttributeMaxDynamicSharedMemorySize, GP<128>::SMEM);
    cudaFuncSetAttribute((const void*)attn_mma,          cudaFuncAttributeMaxDynamicSharedMemorySize, ATT_SMEM);

    // fused preprocessing (cvt + all weight repacks)
    preproc<<<PRE_GRID, 256>>>(src, Wq, Wk, Wv, Wo, W1, W2);

    // fused QKV projection (N=2304, occ 2)
    gemm_mma<4,128,2><<<dim3(3*DD/128, MROWS/128), 256, GP<128>::SMEM>>>(
        srch, wqkv, bq, bk, (float*)bv, nullptr, MROWS, 3*DD, DD);

    // flash attention -> ctx fp16 [B,S,H*DK]
    attn_mma<<<dim3(SS/128, HH, BB), 256, ATT_SMEM>>>(q1, k1, v1, ctxh);

    // out projection (BN=128, split-K 4) -> partials ; LN1(sum + src) -> x
    gemm_mma<5,128,2><<<dim3(DD/128, MROWS/128, 4), 256, GP<128>::SMEM>>>(
        ctxh, wo, bo, nullptr, pp, nullptr, MROWS, DD, DD);
    ln_k<4,1><<<MROWS, 256>>>(pp, src, ln1w, ln1b, px, xh);

    // FF1 (BN=128, relu -> fp16)
    gemm_mma<2,128,2><<<dim3(DFF/128, MROWS/128), 256, GP<128>::SMEM>>>(
        xh, w1, b1, nullptr, nullptr, ffh, MROWS, DFF, DD);

    // FF2 (BN=128, split-K 4) -> partials ; LN2(sum + x) -> out
    gemm_mma<5,128,2><<<dim3(DD/128, MROWS/128, 4), 256, GP<128>::SMEM>>>(
        ffh, w2, b2, nullptr, pp, nullptr, MROWS, DD, DFF);
    ln_k<4,0><<<MROWS, 256>>>(pp, px, ln2w, ln2b, out, nullptr);
}

// round 17
// speedup vs baseline: 1.6340x; 1.6340x over previous
#include <cuda_runtime.h>
#include <cuda_fp16.h>
#include <cstdint>
#include <math.h>

#define BB 2
#define SS 2048
#define DD 768
#define HH 12
#define DKK 64
#define DFF 3072
#define MROWS (BB*SS)   // 4096

// ======================= device scratch (no allocs allowed) ================
__device__ float g_p[4*MROWS*DD];   // split-K partials (bias folded into z=0)
__device__ float g_x[MROWS*DD];     // post-LN1 fp32 (residual for LN2)
// fp16 activations / weights
__device__ __half s_srch[MROWS*DD];
__device__ __half s_ctxh[MROWS*DD];
__device__ __half s_xh[MROWS*DD];
__device__ __half s_ffh[MROWS*DFF];
__device__ __half a_q[BB*HH*SS*DKK];
__device__ __half a_k[BB*HH*SS*DKK];
__device__ __half a_v[BB*HH*SS*DKK];
__device__ __half w_qkv[3*DD*DD];   // [2304, 768]
__device__ __half w_o[DD*DD];
__device__ __half w_1[DFF*DD];
__device__ __half w_2[DD*DFF];

// ======================= PTX helpers (stable ISA only) =====================
__device__ __forceinline__ uint32_t smem_u32(const void* p) {
    uint32_t a;
    asm("{ .reg .u64 t; cvta.to.shared.u64 t, %1; cvt.u32.u64 %0, t; }" : "=r"(a) : "l"(p));
    return a;
}
#define CP_ASYNC16(dst, src) \
    asm volatile("cp.async.cg.shared.global [%0], [%1], 16;" :: "r"(dst), "l"(src) : "memory")
#define CP_COMMIT() asm volatile("cp.async.commit_group;" ::: "memory")
#define CP_WAIT(n)  asm volatile("cp.async.wait_group %0;" :: "n"(n) : "memory")

__device__ __forceinline__ void ldm_x4(uint32_t* r, uint32_t addr) {
    asm volatile("ldmatrix.sync.aligned.m8n8.x4.shared.b16 {%0,%1,%2,%3}, [%4];"
        : "=r"(r[0]), "=r"(r[1]), "=r"(r[2]), "=r"(r[3]) : "r"(addr));
}
__device__ __forceinline__ void ldm_x4_t(uint32_t* r, uint32_t addr) {
    asm volatile("ldmatrix.sync.aligned.m8n8.x4.trans.shared.b16 {%0,%1,%2,%3}, [%4];"
        : "=r"(r[0]), "=r"(r[1]), "=r"(r[2]), "=r"(r[3]) : "r"(addr));
}
__device__ __forceinline__ void mma_f16(float* c, const uint32_t* a, const uint32_t* b) {
    asm volatile("mma.sync.aligned.m16n8k16.row.col.f32.f16.f16.f32 "
        "{%0,%1,%2,%3}, {%4,%5,%6,%7}, {%8,%9}, {%0,%1,%2,%3};"
        : "+f"(c[0]), "+f"(c[1]), "+f"(c[2]), "+f"(c[3])
        : "r"(a[0]), "r"(a[1]), "r"(a[2]), "r"(a[3]), "r"(b[0]), "r"(b[1]));
}
__device__ __forceinline__ float ex2(float x) {
    float y; asm("ex2.approx.ftz.f32 %0, %1;" : "=f"(y) : "f"(x)); return y;
}
__device__ __forceinline__ uint32_t pack_h2(float v0, float v1) {
    uint32_t r;
    asm("cvt.rn.f16x2.f32 %0, %1, %2;" : "=r"(r) : "f"(v1), "f"(v0));
    return r;
}

static __device__ __constant__ const float QSCALE_D = 0.125f * 1.44269504088896340736f;

// ======================= fused preprocessing kernel ========================
static constexpr int NCVT = (MROWS * DD) / 256;   // 12288
static constexpr int NQKV = 2 * 24 * 3 * HH;      // 1728
static constexpr int NWO  = 24 * 24;              // 576
static constexpr int NW1  = 96 * 24;              // 2304
static constexpr int NW2  = 24 * 96;              // 2304
static constexpr int PRE_GRID = NCVT + NQKV + NWO + NW1 + NW2;

__global__ void preproc(const float* __restrict__ src,
                        const float* __restrict__ Wq, const float* __restrict__ Wk,
                        const float* __restrict__ Wv, const float* __restrict__ Wo,
                        const float* __restrict__ W1, const float* __restrict__ W2)
{
    int blk = blockIdx.x;
    if (blk < NCVT) {
        int i = blk * 256 + threadIdx.x;
        s_srch[i] = __float2half_rn(src[i]);
        return;
    }
    blk -= NCVT;

    __shared__ float t[32][33];
    const int tx = threadIdx.x & 31, ty = threadIdx.x >> 5;

    const float* W; __half* o;
    int n0, k0, Kst;
    size_t rowoff = 0;
    if (blk < NQKV) {
        const int z = blk / 48, rem = blk % 48;
        const int sel = z / HH, h = z % HH;
        W = (sel == 0 ? Wq : sel == 1 ? Wk : Wv) + (size_t)h * DD * DKK;
        n0 = (rem % 2) * 32;
        k0 = (rem / 2) * 32;
        Kst = DD;
        o = w_qkv;
        rowoff = (size_t)sel * DD + h * DKK;
        #pragma unroll
        for (int r = 0; r < 4; r++)
            t[ty + 8 * r][tx] = W[(size_t)(k0 + ty + 8 * r) * DKK + n0 + tx];
        __syncthreads();
        #pragma unroll
        for (int r = 0; r < 4; r++)
            o[(rowoff + n0 + ty + 8 * r) * Kst + k0 + tx] =
                __float2half_rn(t[tx][ty + 8 * r]);
        return;
    }
    blk -= NQKV;
    int N;
    if (blk < NWO)      { W = Wo; o = w_o; N = DD;  Kst = DD;  n0 = (blk % 24) * 32; k0 = (blk / 24) * 32; }
    else if ((blk -= NWO) < NW1) { W = W1; o = w_1; N = DFF; Kst = DD;  n0 = (blk % 96) * 32; k0 = (blk / 96) * 32; }
    else                { blk -= NW1; W = W2; o = w_2; N = DD; Kst = DFF; n0 = (blk % 24) * 32; k0 = (blk / 24) * 32; }
    #pragma unroll
    for (int r = 0; r < 4; r++)
        t[ty + 8 * r][tx] = W[(size_t)(k0 + ty + 8 * r) * N + n0 + tx];
    __syncthreads();
    #pragma unroll
    for (int r = 0; r < 4; r++)
        o[(size_t)(n0 + ty + 8 * r) * Kst + k0 + tx] = __float2half_rn(t[tx][ty + 8 * r]);
}

// ======================= mma.sync fp16 GEMM (K-stage = 64) =================
// Double-buffered (c&1), two barriers/stage — proven R14 structure, but each
// stage now covers K=64 (halves barrier count, doubles MMA per barrier-pair).
// MODE 2: relu(acc+bias) -> fp16 row-major
// MODE 4: fused QKV epilogue: Q (scaled) / K / V fp16 [B,H,S,DK]
// MODE 5: split-K partial: acc (+bias iff z==0) -> fp32 at C + z*M*N
static constexpr int RS = 144;   // 64 fp16 (128B) + 16B pad

template<int BN> struct GP {
    static constexpr int A_BYTES = 128 * RS;                 // 18432
    static constexpr int B_BYTES = BN * RS;
    static constexpr int STGB    = A_BYTES + B_BYTES;
    static constexpr int SMEM    = 2 * STGB;                 // 73728 @BN=128
    static constexpr int NTW     = BN / 16;
    static constexpr int NPB     = BN / 32;
    static constexpr int CPT     = (1024 + 8 * BN) / 256;    // 16B chunks/thread
};

template<int MODE, int BN, int MINB>
__global__ void __launch_bounds__(256, MINB) gemm_mma(
    const __half* __restrict__ A, const __half* __restrict__ B,
    const float* __restrict__ bias, const float* __restrict__ res,
    float* __restrict__ C, __half* __restrict__ Cs,
    int M, int N, int K)
{
    using P = GP<BN>;
    extern __shared__ char sb[];
    const uint32_t sbu = smem_u32(sb);
    const int tid  = threadIdx.x;
    const int wid  = tid >> 5;
    const int lane = tid & 31;
    const int wm   = wid & 3;
    const int wn   = wid >> 2;

    const int z      = (MODE == 5) ? blockIdx.z : 0;
    const int kLen   = (MODE == 5) ? K / ((int)gridDim.z) : K;
    const int kc0    = z * kLen;

    const int rowBase = blockIdx.y << 7;
    const int colBase = blockIdx.x * BN;
    const __half* gA = A + (size_t)rowBase * K;
    const __half* gB = B + (size_t)colBase * K;

    // per-thread cp.async slots: row has 8 x 16B chunks (64 fp16)
    int ld_mat[P::CPT], ld_r[P::CPT], ld_q[P::CPT];
    #pragma unroll
    for (int i = 0; i < P::CPT; i++) {
        int slot = (i << 8) + tid;
        int mat, rem;
        if (slot < 1024) { mat = 0; rem = slot; }
        else             { mat = 1; rem = slot - 1024; }
        ld_mat[i] = mat; ld_r[i] = rem >> 3; ld_q[i] = rem & 7;
    }

    auto load_stage = [&](int kc, int buf) {
        const uint32_t base = sbu + buf * P::STGB;
        #pragma unroll
        for (int i = 0; i < P::CPT; i++) {
            const __half* src = (ld_mat[i] == 0 ? gA : gB)
                                + (size_t)ld_r[i] * K + kc + (ld_q[i] << 3);
            uint32_t dst = base + ld_mat[i] * P::A_BYTES + ld_r[i] * RS + (ld_q[i] << 4);
            CP_ASYNC16(dst, src);
        }
        CP_COMMIT();
    };

    float acc[2][P::NTW][4];
    #pragma unroll
    for (int mt = 0; mt < 2; mt++)
        #pragma unroll
        for (int nt = 0; nt < P::NTW; nt++)
            #pragma unroll
            for (int j = 0; j < 4; j++) acc[mt][nt][j] = 0.0f;

    const uint32_t aAddr = (uint32_t)((wm * 32 + (lane & 15)) * RS + (lane >> 4) * 16);
    const uint32_t bAddr = (uint32_t)((wn * (BN/2) + ((lane >> 4) << 3) + (lane & 7)) * RS
                                      + ((lane >> 3) & 1) * 16);

    const int nStages = kLen >> 6;
    load_stage(kc0, 0);

    for (int c = 0; c < nStages; c++) {
        if (c + 1 < nStages) load_stage(kc0 + ((c + 1) << 6), (c + 1) & 1);
        if (c + 1 < nStages) { CP_WAIT(1); } else { CP_WAIT(0); }
        __syncthreads();

        const uint32_t base = sbu + (c & 1) * P::STGB;
        #pragma unroll
        for (int ks = 0; ks < 4; ks++) {
            const uint32_t ko = ks * 32;
            uint32_t bf[P::NTW*2];
            #pragma unroll
            for (int np = 0; np < P::NPB; np++)
                ldm_x4(bf + np * 4, base + P::A_BYTES + bAddr + np * 16 * RS + ko);
            #pragma unroll
            for (int mt = 0; mt < 2; mt++) {
                uint32_t ah[4];
                ldm_x4(ah, base + aAddr + mt * 16 * RS + ko);
                #pragma unroll
                for (int nt = 0; nt < P::NTW; nt++)
                    mma_f16(acc[mt][nt], ah, bf + nt * 2);
            }
        }
        __syncthreads();
    }

    // ---------------- epilogue ----------------
    const int g  = lane >> 2;
    const int tc = (lane & 3) << 1;

    #pragma unroll
    for (int mt = 0; mt < 2; mt++) {
        #pragma unroll
        for (int half_i = 0; half_i < 2; half_i++) {
            const int orow = rowBase + wm * 32 + mt * 16 + g + half_i * 8;
            #pragma unroll
            for (int nt = 0; nt < P::NTW; nt++) {
                const int col = colBase + wn * (BN/2) + nt * 8 + tc;
                float a0 = acc[mt][nt][half_i * 2 + 0];
                float a1 = acc[mt][nt][half_i * 2 + 1];
                if (MODE == 4) {
                    const int sel = col / DD;
                    const int lc  = col - sel * DD;
                    const float* bptr = sel == 0 ? bias : sel == 1 ? res : (const float*)C;
                    float v0 = a0 + bptr[lc];
                    float v1 = a1 + bptr[lc + 1];
                    const int b = orow >> 11, s = orow & 2047;
                    const int h = lc >> 6, dk = lc & 63;
                    size_t off = (((size_t)b * HH + h) * SS + s) * DKK + dk;
                    if (sel == 0) { v0 *= QSCALE_D; v1 *= QSCALE_D; }
                    __half* dst = sel == 0 ? a_q : sel == 1 ? a_k : a_v;
                    *(uint32_t*)(dst + off) = pack_h2(v0, v1);
                } else if (MODE == 5) {
                    float b0 = (z == 0) ? bias[col] : 0.0f;
                    float b1 = (z == 0) ? bias[col + 1] : 0.0f;
                    *(float2*)(C + (size_t)z * M * N + (size_t)orow * N + col)
                        = make_float2(a0 + b0, a1 + b1);
                } else {
                    float v0 = fmaxf(a0 + bias[col], 0.0f);
                    float v1 = fmaxf(a1 + bias[col + 1], 0.0f);
                    *(uint32_t*)(Cs + (size_t)orow * N + col) = pack_h2(v0, v1);
                }
            }
        }
    }
}

// ======================= mma.sync flash attention (R14 version) ============
static constexpr int ATT_RS  = 144;
static constexpr int ATT_BUF = 64 * ATT_RS;
static constexpr int ATT_STG = 2 * ATT_BUF;   // 18432 (K,V)
static constexpr int ATT_SMEM = 2 * ATT_STG;  // 36864

__global__ void __launch_bounds__(256, 2) attn_mma(
    const __half* __restrict__ Q, const __half* __restrict__ K,
    const __half* __restrict__ V, __half* __restrict__ Cs)
{
    extern __shared__ char sm[];
    const uint32_t sbu = smem_u32(sm);
    const int qt = blockIdx.x, h = blockIdx.y, b = blockIdx.z;
    const int tid = threadIdx.x, wid = tid >> 5, lane = tid & 31;

    const size_t bh = (size_t)b * HH + h;
    const __half* gQ = Q + (bh * SS + qt * 128) * DKK;
    const __half* gK = K + bh * SS * DKK;
    const __half* gV = V + bh * SS * DKK;

    {
        #pragma unroll
        for (int i = 0; i < 4; i++) {
            int slot = (i << 8) + tid;
            int r = slot >> 3, c = slot & 7;
            CP_ASYNC16(sbu + r * ATT_RS + (c << 4), gQ + r * DKK + (c << 3));
        }
        CP_COMMIT(); CP_WAIT(0);
        __syncthreads();
    }
    uint32_t qf[4][4];
    {
        const uint32_t qa = sbu + (wid * 16 + (lane & 15)) * ATT_RS + ((lane >> 4) << 4);
        #pragma unroll
        for (int ks = 0; ks < 4; ks++) ldm_x4(qf[ks], qa + ks * 32);
    }
    __syncthreads();

    auto load_kv = [&](int t0, int buf) {
        const uint32_t base = sbu + buf * ATT_STG;
        #pragma unroll
        for (int i = 0; i < 4; i++) {
            int slot = (i << 8) + tid;
            int arr = slot >> 9;
            int rem = slot & 511;
            int r = rem >> 3, c = rem & 7;
            const __half* src = (arr == 0 ? gK : gV) + (size_t)(t0 + r) * DKK + (c << 3);
            CP_ASYNC16(base + arr * ATT_BUF + r * ATT_RS + (c << 4), src);
        }
        CP_COMMIT();
    };

    float ctx[8][4];
    #pragma unroll
    for (int nt = 0; nt < 8; nt++)
        #pragma unroll
        for (int j = 0; j < 4; j++) ctx[nt][j] = 0.0f;
    float m0 = -1e30f, m1 = -1e30f, l0 = 0.0f, l1 = 0.0f;

    const uint32_t kAddr = (uint32_t)(((((lane >> 4) << 3) | (lane & 7)) * ATT_RS)
                                      + ((lane >> 3) & 1) * 16);
    const uint32_t vAddr = (uint32_t)((lane & 15) * ATT_RS + ((lane >> 4) << 4));

    load_kv(0, 0);
    #pragma unroll 1
    for (int t = 0; t < SS / 64; t++) {
        if (t + 1 < SS / 64) { load_kv((t + 1) * 64, (t + 1) & 1); CP_WAIT(1); }
        else                 { CP_WAIT(0); }
        __syncthreads();
        const uint32_t base = sbu + (t & 1) * ATT_STG;

        float sa[8][4];
        #pragma unroll
        for (int nt = 0; nt < 8; nt++)
            #pragma unroll
            for (int j = 0; j < 4; j++) sa[nt][j] = 0.0f;
        #pragma unroll
        for (int ks = 0; ks < 4; ks++) {
            #pragma unroll
            for (int np = 0; np < 4; np++) {
                uint32_t kb[4];
                ldm_x4(kb, base + kAddr + np * 16 * ATT_RS + ks * 32);
                mma_f16(sa[2 * np],     qf[ks], kb);
                mma_f16(sa[2 * np + 1], qf[ks], kb + 2);
            }
        }

        float rm0 = -1e30f, rm1 = -1e30f;
        #pragma unroll
        for (int nt = 0; nt < 8; nt++) {
            rm0 = fmaxf(rm0, fmaxf(sa[nt][0], sa[nt][1]));
            rm1 = fmaxf(rm1, fmaxf(sa[nt][2], sa[nt][3]));
        }
        rm0 = fmaxf(rm0, __shfl_xor_sync(0xFFFFFFFFu, rm0, 1));
        rm0 = fmaxf(rm0, __shfl_xor_sync(0xFFFFFFFFu, rm0, 2));
        rm1 = fmaxf(rm1, __shfl_xor_sync(0xFFFFFFFFu, rm1, 1));
        rm1 = fmaxf(rm1, __shfl_xor_sync(0xFFFFFFFFu, rm1, 2));
        const float nm0 = fmaxf(m0, rm0), nm1 = fmaxf(m1, rm1);
        const float c0 = ex2(m0 - nm0), c1 = ex2(m1 - nm1);
        l0 *= c0; l1 *= c1;
        #pragma unroll
        for (int nt = 0; nt < 8; nt++) {
            ctx[nt][0] *= c0; ctx[nt][1] *= c0;
            ctx[nt][2] *= c1; ctx[nt][3] *= c1;
        }
        float s0 = 0.0f, s1 = 0.0f;
        #pragma unroll
        for (int nt = 0; nt < 8; nt++) {
            float p0 = ex2(sa[nt][0] - nm0); sa[nt][0] = p0; s0 += p0;
            float p1 = ex2(sa[nt][1] - nm0); sa[nt][1] = p1; s0 += p1;
            float p2 = ex2(sa[nt][2] - nm1); sa[nt][2] = p2; s1 += p2;
            float p3 = ex2(sa[nt][3] - nm1); sa[nt][3] = p3; s1 += p3;
        }
        s0 += __shfl_xor_sync(0xFFFFFFFFu, s0, 1);
        s0 += __shfl_xor_sync(0xFFFFFFFFu, s0, 2);
        s1 += __shfl_xor_sync(0xFFFFFFFFu, s1, 1);
        s1 += __shfl_xor_sync(0xFFFFFFFFu, s1, 2);
        l0 += s0; l1 += s1; m0 = nm0; m1 = nm1;

        #pragma unroll
        for (int ks = 0; ks < 4; ks++) {
            uint32_t ph[4];
            ph[0] = pack_h2(sa[2 * ks][0],     sa[2 * ks][1]);
            ph[1] = pack_h2(sa[2 * ks][2],     sa[2 * ks][3]);
            ph[2] = pack_h2(sa[2 * ks + 1][0], sa[2 * ks + 1][1]);
            ph[3] = pack_h2(sa[2 * ks + 1][2], sa[2 * ks + 1][3]);
            const uint32_t vrow = vAddr + ks * 16 * ATT_RS;
            #pragma unroll
            for (int np = 0; np < 4; np++) {
                uint32_t vb[4];
                ldm_x4_t(vb, base + ATT_BUF + vrow + np * 32);
                mma_f16(ctx[2 * np],     ph, vb);
                mma_f16(ctx[2 * np + 1], ph, vb + 2);
            }
        }
        __syncthreads();
    }

    const float i0 = 1.0f / l0, i1 = 1.0f / l1;
    const int g = lane >> 2, tc2 = (lane & 3) << 1;
    const int r0 = qt * 128 + wid * 16 + g;
    const size_t base0 = ((size_t)b * SS + r0) * DD + h * DKK;
    #pragma unroll
    for (int nt = 0; nt < 8; nt++) {
        const int col = nt * 8 + tc2;
        *(uint32_t*)(Cs + base0 + col) = pack_h2(ctx[nt][0] * i0, ctx[nt][1] * i0);
        *(uint32_t*)(Cs + base0 + (size_t)8 * DD + col) = pack_h2(ctx[nt][2] * i1, ctx[nt][3] * i1);
    }
}

// ======================= LayerNorm over (sum of NP partials + res) =========
template<int NP, int WB>
__global__ __launch_bounds__(256)
void ln_k(const float* __restrict__ parts, const float* __restrict__ res,
          const float* __restrict__ w, const float* __restrict__ bsh,
          float* __restrict__ out, __half* __restrict__ oh)
{
    const size_t row = blockIdx.x;
    float xv[3];
    float s = 0.0f, s2 = 0.0f;
    #pragma unroll
    for (int it = 0; it < 3; it++) {
        int i = threadIdx.x + it * 256;
        float v = res[row * DD + i];
        #pragma unroll
        for (int p = 0; p < NP; p++)
            v += parts[(size_t)p * MROWS * DD + row * DD + i];
        xv[it] = v; s += v; s2 += v * v;
    }
    #pragma unroll
    for (int o = 16; o > 0; o >>= 1) {
        s  += __shfl_xor_sync(0xFFFFFFFFu, s,  o);
        s2 += __shfl_xor_sync(0xFFFFFFFFu, s2, o);
    }
    __shared__ float ws[8], ws2[8];
    const int wid = threadIdx.x >> 5, lane = threadIdx.x & 31;
    if (lane == 0) { ws[wid] = s; ws2[wid] = s2; }
    __syncthreads();
    float ts = 0.0f, ts2 = 0.0f;
    #pragma unroll
    for (int i = 0; i < 8; i++) { ts += ws[i]; ts2 += ws2[i]; }
    const float mu   = ts  * (1.0f / DD);
    const float var  = ts2 * (1.0f / DD) - mu * mu;
    const float rstd = rsqrtf(var + 1e-5f);
    #pragma unroll
    for (int it = 0; it < 3; it++) {
        int i = threadIdx.x + it * 256;
        float r = (xv[it] - mu) * rstd * w[i] + bsh[i];
        if (out) out[row * DD + i] = r;
        if (WB) oh[row * DD + i] = __float2half_rn(r);
    }
}

// ======================= launch ============================================
template<typename T>
static void* sym_addr(T& sym) {
    void* p = nullptr;
    cudaGetSymbolAddress(&p, sym);
    return p;
}

extern "C" void kernel_launch(void* const* d_in, const int* in_sizes, int n_in,
                              void* d_out, int out_size)
{
    const float* src  = (const float*)d_in[0];
    const float* Wq   = (const float*)d_in[1];
    const float* bq   = (const float*)d_in[2];
    const float* Wk   = (const float*)d_in[3];
    const float* bk   = (const float*)d_in[4];
    const float* Wv   = (const float*)d_in[5];
    const float* bv   = (const float*)d_in[6];
    const float* Wo   = (const float*)d_in[7];
    const float* bo   = (const float*)d_in[8];
    const float* ln1w = (const float*)d_in[9];
    const float* ln1b = (const float*)d_in[10];
    const float* W1   = (const float*)d_in[11];
    const float* b1   = (const float*)d_in[12];
    const float* W2   = (const float*)d_in[13];
    const float* b2   = (const float*)d_in[14];
    const float* ln2w = (const float*)d_in[15];
    const float* ln2b = (const float*)d_in[16];
    float* out = (float*)d_out;

    float* pp   = (float*)sym_addr(g_p);
    float* px   = (float*)sym_addr(g_x);

    __half* ctxh = (__half*)sym_addr(s_ctxh);
    __half* srch = (__half*)sym_addr(s_srch);
    __half* xh   = (__half*)sym_addr(s_xh);
    __half* ffh  = (__half*)sym_addr(s_ffh);
    __half* q1   = (__half*)sym_addr(a_q);
    __half* k1   = (__half*)sym_addr(a_k);
    __half* v1   = (__half*)sym_addr(a_v);
    __half* wqkv = (__half*)sym_addr(w_qkv);
    __half* wo   = (__half*)sym_addr(w_o);
    __half* w1   = (__half*)sym_addr(w_1);
    __half* w2   = (__half*)sym_addr(w_2);

    cudaFuncSetAttribute((const void*)gemm_mma<4,128,2>, cudaFuncAttributeMaxDynamicSharedMemorySize, GP<128>::SMEM);
    cudaFuncSetAttribute((const void*)gemm_mma<2,128,2>, cudaFuncAttributeMaxDynamicSharedMemorySize, GP<128>::SMEM);
    cudaFuncSetAttribute((const void*)gemm_mma<5,128,2>, cudaFuncAttributeMaxDynamicSharedMemorySize, GP<128>::SMEM);
    cudaFuncSetAttribute((const void*)attn_mma,          cudaFuncAttributeMaxDynamicSharedMemorySize, ATT_SMEM);

    // fused preprocessing (cvt + all weight repacks)
    preproc<<<PRE_GRID, 256>>>(src, Wq, Wk, Wv, Wo, W1, W2);

    // fused QKV projection (N=2304, occ 2)
    gemm_mma<4,128,2><<<dim3(3*DD/128, MROWS/128), 256, GP<128>::SMEM>>>(
        srch, wqkv, bq, bk, (float*)bv, nullptr, MROWS, 3*DD, DD);

    // flash attention -> ctx fp16 [B,S,H*DK]
    attn_mma<<<dim3(SS/128, HH, BB), 256, ATT_SMEM>>>(q1, k1, v1, ctxh);

    // out projection (BN=128, split-K 4) -> partials ; LN1(sum + src) -> x
    gemm_mma<5,128,2><<<dim3(DD/128, MROWS/128, 4), 256, GP<128>::SMEM>>>(
        ctxh, wo, bo, nullptr, pp, nullptr, MROWS, DD, DD);
    ln_k<4,1><<<MROWS, 256>>>(pp, src, ln1w, ln1b, px, xh);

    // FF1 (BN=128, relu -> fp16)
    gemm_mma<2,128,2><<<dim3(DFF/128, MROWS/128), 256, GP<128>::SMEM>>>(
        xh, w1, b1, nullptr, nullptr, ffh, MROWS, DFF, DD);

    // FF2 (BN=128, split-K 4) -> partials ; LN2(sum + x) -> out
    gemm_mma<5,128,2><<<dim3(DD/128, MROWS/128, 4), 256, GP<128>::SMEM>>>(
        ffh, w2, b2, nullptr, pp, nullptr, MROWS, DD, DFF);
    ln_k<4,0><<<MROWS, 256>>>(pp, px, ln2w, ln2b, out, nullptr);
}